// round 3
// baseline (speedup 1.0000x reference)
#include <cuda_runtime.h>

// Problem constants
#define NB 4
#define NT 2048
#define NC 1024
#define NH 16
#define ND 64
#define NM (NB * NT)     // 8192 rows
#define NF (3 * NC)      // 3072 qkv features

// Scratch: __device__ globals (allocation inside kernel_launch is forbidden)
__device__ float g_qkv[25165824];   // [NM][NF]  = 8192*3072
__device__ float g_attn[8388608];   // [NM][NC]  = 8192*1024

// ---------------------------------------------------------------------------
// NT SGEMM: C[m][n] = sum_k A[m][k] * B[n][k]
// 128x128 block tile, BK=16, 256 threads, 8x8 register tile per thread.
// Smem tiles stored transposed [k][m] with +4 padding to reduce store conflicts.
// M, N, K all multiples of 128/16 for our shapes -> no bounds checks.
// ---------------------------------------------------------------------------
__device__ __forceinline__ void sgemm_nt_body(const float* __restrict__ A,
                                              const float* __restrict__ Bw,
                                              float* __restrict__ Cc,
                                              int N, int K)
{
    __shared__ float As[16][132];
    __shared__ float Bs[16][132];

    const int tid = threadIdx.x;
    const int ty = tid >> 4;          // 0..15
    const int tx = tid & 15;          // 0..15
    const int m0 = blockIdx.y << 7;
    const int n0 = blockIdx.x << 7;

    float acc[8][8];
#pragma unroll
    for (int i = 0; i < 8; i++)
#pragma unroll
        for (int j = 0; j < 8; j++) acc[i][j] = 0.f;

    const int lrow = tid >> 2;          // 0..63
    const int lcol = (tid & 3) << 2;    // 0,4,8,12
    const float* Ag = A + (long long)(m0 + lrow) * K + lcol;
    const float* Bg = Bw + (long long)(n0 + lrow) * K + lcol;

    for (int kt = 0; kt < K; kt += 16) {
#pragma unroll
        for (int it = 0; it < 2; it++) {
            const float4 av = *(const float4*)(Ag + (long long)(it * 64) * K + kt);
            const float4 bv = *(const float4*)(Bg + (long long)(it * 64) * K + kt);
            const int r = lrow + it * 64;
            As[lcol + 0][r] = av.x; As[lcol + 1][r] = av.y;
            As[lcol + 2][r] = av.z; As[lcol + 3][r] = av.w;
            Bs[lcol + 0][r] = bv.x; Bs[lcol + 1][r] = bv.y;
            Bs[lcol + 2][r] = bv.z; Bs[lcol + 3][r] = bv.w;
        }
        __syncthreads();

#pragma unroll
        for (int k = 0; k < 16; k++) {
            float a[8], b[8];
            *(float4*)&a[0] = *(const float4*)&As[k][ty * 8];
            *(float4*)&a[4] = *(const float4*)&As[k][ty * 8 + 4];
            *(float4*)&b[0] = *(const float4*)&Bs[k][tx * 8];
            *(float4*)&b[4] = *(const float4*)&Bs[k][tx * 8 + 4];
#pragma unroll
            for (int i = 0; i < 8; i++)
#pragma unroll
                for (int j = 0; j < 8; j++)
                    acc[i][j] += a[i] * b[j];
        }
        __syncthreads();
    }

#pragma unroll
    for (int i = 0; i < 8; i++) {
        float* Cr = Cc + (long long)(m0 + ty * 8 + i) * N + n0 + tx * 8;
        *(float4*)(Cr + 0) = make_float4(acc[i][0], acc[i][1], acc[i][2], acc[i][3]);
        *(float4*)(Cr + 4) = make_float4(acc[i][4], acc[i][5], acc[i][6], acc[i][7]);
    }
}

__global__ __launch_bounds__(256) void qkv_gemm(const float* __restrict__ x,
                                                const float* __restrict__ w)
{
    sgemm_nt_body(x, w, g_qkv, NF, NC);
}

__global__ __launch_bounds__(256) void proj_gemm(const float* __restrict__ w,
                                                 float* __restrict__ out)
{
    sgemm_nt_body(g_attn, w, out, NC, NC);
}

// ---------------------------------------------------------------------------
// Flash attention, fp32, causal. One block = one (b,h) x 64-query tile.
// 256 threads: thread (tq,tk) owns S rows 4tq..+3, cols 4tk..+3, and the same
// mapping for the O accumulator (cols = head dims). Online softmax stats per
// q-row replicated across the 16-lane row group via xor-shuffles.
// Q,K staged transposed [d][row] (q-loads broadcast, k-loads spread banks);
// P tile is written back into the K buffer (stride 68) between the two GEMMs.
// ---------------------------------------------------------------------------
#define KSTR 68
#define ATTN_SMEM ((4096 + 64 * KSTR + 4096) * 4)   // Qs + Ks + Vs = 50176 B

__global__ __launch_bounds__(256) void attn_kernel()
{
    extern __shared__ float smem[];
    float* Qs = smem;                   // [64][64]   transposed [d][q]
    float* Ks = smem + 4096;            // [64][68]   transposed [d][k]; reused as P[q][k]
    float* Vs = Ks + 64 * KSTR;         // [64][64]   natural [k][d]

    const int tid = threadIdx.x;
    const int tq = tid >> 4;            // 0..15
    const int tk = tid & 15;            // 0..15
    const int bh = blockIdx.y;
    const int b = bh >> 4;
    const int h = bh & 15;
    const int q0 = blockIdx.x << 6;

    const float* base = g_qkv + (long long)b * NT * NF + h * ND;

    // Load Q tile (transposed + pre-scaled by 1/sqrt(64))
    {
        const int r = tid >> 4;
        const int d4 = (tid & 15) << 2;
#pragma unroll
        for (int it = 0; it < 4; it++) {
            const int rr = r + it * 16;
            const float4 v = *(const float4*)(base + (long long)(q0 + rr) * NF + d4);
            Qs[(d4 + 0) * 64 + rr] = v.x * 0.125f;
            Qs[(d4 + 1) * 64 + rr] = v.y * 0.125f;
            Qs[(d4 + 2) * 64 + rr] = v.z * 0.125f;
            Qs[(d4 + 3) * 64 + rr] = v.w * 0.125f;
        }
    }

    float o[4][4];
    float mr[4], lr[4];
#pragma unroll
    for (int i = 0; i < 4; i++) {
        mr[i] = -1e30f;
        lr[i] = 0.f;
#pragma unroll
        for (int j = 0; j < 4; j++) o[i][j] = 0.f;
    }

    const int kbmax = blockIdx.x;
    for (int kb = 0; kb <= kbmax; kb++) {
        // Load K (transposed) and V (natural) tiles
        {
            const int r = tid >> 4;
            const int d4 = (tid & 15) << 2;
            const float* kp = base + NC + (long long)(kb * 64) * NF;
            const float* vp = base + 2 * NC + (long long)(kb * 64) * NF;
#pragma unroll
            for (int it = 0; it < 4; it++) {
                const int rr = r + it * 16;
                const float4 kv = *(const float4*)(kp + (long long)rr * NF + d4);
                Ks[(d4 + 0) * KSTR + rr] = kv.x;
                Ks[(d4 + 1) * KSTR + rr] = kv.y;
                Ks[(d4 + 2) * KSTR + rr] = kv.z;
                Ks[(d4 + 3) * KSTR + rr] = kv.w;
                const float4 vv = *(const float4*)(vp + (long long)rr * NF + d4);
                *(float4*)(Vs + rr * 64 + d4) = vv;
            }
        }
        __syncthreads();

        // S = Q K^T
        float s[4][4];
#pragma unroll
        for (int i = 0; i < 4; i++)
#pragma unroll
            for (int j = 0; j < 4; j++) s[i][j] = 0.f;

#pragma unroll 8
        for (int d = 0; d < 64; d++) {
            const float4 qf = *(const float4*)(Qs + d * 64 + (tq << 2));
            const float4 kf = *(const float4*)(Ks + d * KSTR + (tk << 2));
            const float qa[4] = {qf.x, qf.y, qf.z, qf.w};
            const float ka[4] = {kf.x, kf.y, kf.z, kf.w};
#pragma unroll
            for (int i = 0; i < 4; i++)
#pragma unroll
                for (int j = 0; j < 4; j++)
                    s[i][j] += qa[i] * ka[j];
        }

        // Causal mask on the diagonal tile (kb*64 == q0 there)
        if (kb == kbmax) {
#pragma unroll
            for (int i = 0; i < 4; i++)
#pragma unroll
                for (int j = 0; j < 4; j++)
                    if ((tk * 4 + j) > (tq * 4 + i)) s[i][j] = -1e30f;
        }

        // Online softmax (row stats replicated across the 16-lane row group)
#pragma unroll
        for (int i = 0; i < 4; i++) {
            float mx = fmaxf(fmaxf(s[i][0], s[i][1]), fmaxf(s[i][2], s[i][3]));
#pragma unroll
            for (int off = 1; off < 16; off <<= 1)
                mx = fmaxf(mx, __shfl_xor_sync(0xffffffffu, mx, off));
            const float mnew = fmaxf(mr[i], mx);
            const float alpha = __expf(mr[i] - mnew);
            float ls = 0.f;
#pragma unroll
            for (int j = 0; j < 4; j++) {
                s[i][j] = __expf(s[i][j] - mnew);
                ls += s[i][j];
            }
#pragma unroll
            for (int off = 1; off < 16; off <<= 1)
                ls += __shfl_xor_sync(0xffffffffu, ls, off);
            lr[i] = lr[i] * alpha + ls;
            mr[i] = mnew;
#pragma unroll
            for (int j = 0; j < 4; j++) o[i][j] *= alpha;
        }

        // Stage P into the K buffer as P[q][k] (stride KSTR)
        __syncthreads();
#pragma unroll
        for (int i = 0; i < 4; i++)
            *(float4*)(Ks + (tq * 4 + i) * KSTR + tk * 4) =
                make_float4(s[i][0], s[i][1], s[i][2], s[i][3]);
        __syncthreads();

        // O += P @ V
#pragma unroll 4
        for (int k0 = 0; k0 < 64; k0 += 4) {
            float pf[4][4], vf[4][4];
#pragma unroll
            for (int i = 0; i < 4; i++)
                *(float4*)&pf[i][0] = *(const float4*)(Ks + (tq * 4 + i) * KSTR + k0);
#pragma unroll
            for (int kk = 0; kk < 4; kk++)
                *(float4*)&vf[kk][0] = *(const float4*)(Vs + (k0 + kk) * 64 + (tk << 2));
#pragma unroll
            for (int i = 0; i < 4; i++)
#pragma unroll
                for (int kk = 0; kk < 4; kk++)
#pragma unroll
                    for (int j = 0; j < 4; j++)
                        o[i][j] += pf[i][kk] * vf[kk][j];
        }
        __syncthreads();   // protect Ks/Vs before next tile's loads
    }

    // Epilogue: normalize and write [B,T,H*D]
#pragma unroll
    for (int i = 0; i < 4; i++) {
        const float inv = 1.0f / lr[i];
        const int t = q0 + tq * 4 + i;
        const float4 r = make_float4(o[i][0] * inv, o[i][1] * inv,
                                     o[i][2] * inv, o[i][3] * inv);
        *(float4*)(g_attn + (long long)(b * NT + t) * NC + h * ND + tk * 4) = r;
    }
}

// ---------------------------------------------------------------------------
// Launch: qkv GEMM -> attention -> proj GEMM (default stream, graph-capturable)
// ---------------------------------------------------------------------------
extern "C" void kernel_launch(void* const* d_in, const int* in_sizes, int n_in,
                              void* d_out, int out_size)
{
    const float* x      = (const float*)d_in[0];
    const float* w_qkv  = (const float*)d_in[1];
    const float* w_proj = (const float*)d_in[2];
    float* out = (float*)d_out;

    qkv_gemm<<<dim3(NF / 128, NM / 128), 256>>>(x, w_qkv);

    cudaFuncSetAttribute(attn_kernel,
                         cudaFuncAttributeMaxDynamicSharedMemorySize, ATTN_SMEM);
    attn_kernel<<<dim3(NT / 64, NB * NH), 256, ATTN_SMEM>>>();

    proj_gemm<<<dim3(NC / 128, NM / 128), 256>>>(w_proj, out);
}

// round 5
// speedup vs baseline: 1.5891x; 1.5891x over previous
#include <cuda_runtime.h>
#include <cuda_bf16.h>
#include <cstdint>

// Problem constants
#define NB 4
#define NT 2048
#define NC 1024
#define NH 16
#define ND 64
#define NM (NB * NT)     // 8192 rows
#define NF (3 * NC)      // 3072 qkv features

// ---------------------------------------------------------------------------
// Scratch (__device__ globals; allocation in kernel_launch is forbidden)
// ---------------------------------------------------------------------------
__device__ float g_qkv[NM * NF];    // fp32 qkv  [8192][3072]
__device__ float g_attn[NM * NC];   // fp32 attn out [8192][1024]

// bf16 hi/lo split operands, plain row-major [R][1024]
__device__ __nv_bfloat16 g_x_hi[NM * NC],  g_x_lo[NM * NC];
__device__ __nv_bfloat16 g_wq_hi[NF * NC], g_wq_lo[NF * NC];
__device__ __nv_bfloat16 g_wp_hi[NC * NC], g_wp_lo[NC * NC];
__device__ __nv_bfloat16 g_at_hi[NM * NC], g_at_lo[NM * NC];

// ---------------------------------------------------------------------------
// PTX helpers (arch-agnostic: mma.sync / ldmatrix / cp.async only)
// ---------------------------------------------------------------------------
__device__ __forceinline__ uint32_t smem_u32(const void* p) {
    uint32_t a;
    asm("{ .reg .u64 t; cvta.to.shared.u64 t, %1; cvt.u32.u64 %0, t; }"
        : "=r"(a) : "l"(p));
    return a;
}

__device__ __forceinline__ void cp_async16(uint32_t dst, const void* src) {
    asm volatile("cp.async.cg.shared.global [%0], [%1], 16;" :: "r"(dst), "l"(src));
}

__device__ __forceinline__ void ldsm4(uint32_t* r, uint32_t addr) {
    asm volatile("ldmatrix.sync.aligned.m8n8.x4.shared.b16 {%0,%1,%2,%3}, [%4];"
                 : "=r"(r[0]), "=r"(r[1]), "=r"(r[2]), "=r"(r[3]) : "r"(addr));
}

__device__ __forceinline__ void mma_bf16(float* c, const uint32_t* a,
                                         uint32_t b0, uint32_t b1) {
    asm volatile(
        "mma.sync.aligned.m16n8k16.row.col.f32.bf16.bf16.f32 "
        "{%0,%1,%2,%3}, {%4,%5,%6,%7}, {%8,%9}, {%0,%1,%2,%3};"
        : "+f"(c[0]), "+f"(c[1]), "+f"(c[2]), "+f"(c[3])
        : "r"(a[0]), "r"(a[1]), "r"(a[2]), "r"(a[3]), "r"(b0), "r"(b1));
}

// ---------------------------------------------------------------------------
// Split prep: fp32 [R][1024] -> hi/lo bf16, row-major, coalesced.
// grid = R blocks x 256 threads; thread handles 4 consecutive columns.
// ---------------------------------------------------------------------------
__device__ __forceinline__ void split_body(const float* __restrict__ src,
                                           __nv_bfloat16* __restrict__ hi,
                                           __nv_bfloat16* __restrict__ lo) {
    const int r = blockIdx.x;
    const int c4 = threadIdx.x << 2;
    const float4 v = *(const float4*)(src + (size_t)r * NC + c4);

    const __nv_bfloat16 h0 = __float2bfloat16(v.x);
    const __nv_bfloat16 h1 = __float2bfloat16(v.y);
    const __nv_bfloat16 h2 = __float2bfloat16(v.z);
    const __nv_bfloat16 h3 = __float2bfloat16(v.w);
    const __nv_bfloat16 l0 = __float2bfloat16(v.x - __bfloat162float(h0));
    const __nv_bfloat16 l1 = __float2bfloat16(v.y - __bfloat162float(h1));
    const __nv_bfloat16 l2 = __float2bfloat16(v.z - __bfloat162float(h2));
    const __nv_bfloat16 l3 = __float2bfloat16(v.w - __bfloat162float(h3));

    uint2 uh, ul;
    uh.x = (uint32_t)__bfloat16_as_ushort(h0) | ((uint32_t)__bfloat16_as_ushort(h1) << 16);
    uh.y = (uint32_t)__bfloat16_as_ushort(h2) | ((uint32_t)__bfloat16_as_ushort(h3) << 16);
    ul.x = (uint32_t)__bfloat16_as_ushort(l0) | ((uint32_t)__bfloat16_as_ushort(l1) << 16);
    ul.y = (uint32_t)__bfloat16_as_ushort(l2) | ((uint32_t)__bfloat16_as_ushort(l3) << 16);

    *(uint2*)(hi + (size_t)r * NC + c4) = uh;
    *(uint2*)(lo + (size_t)r * NC + c4) = ul;
}

__global__ __launch_bounds__(256) void split_x(const float* __restrict__ s)  { split_body(s, g_x_hi,  g_x_lo);  }
__global__ __launch_bounds__(256) void split_wq(const float* __restrict__ s) { split_body(s, g_wq_hi, g_wq_lo); }
__global__ __launch_bounds__(256) void split_wp(const float* __restrict__ s) { split_body(s, g_wp_hi, g_wp_lo); }
__global__ __launch_bounds__(256) void split_at()                            { split_body(g_attn, g_at_hi, g_at_lo); }

// ---------------------------------------------------------------------------
// mma.sync GEMM: C[m][n] = sum_k A[m][k]*B[n][k] (fp32 via bf16 2-term split)
// CTA 128x128, 256 thr (8 warps: wm=wid&3, wn=wid>>2), warp tile 32x64.
// BK=64, double-buffered cp.async (2 x 64KB smem stages).
// Smem tile layout: [128 rows][64 bf16], 128B rows, chunk swizzle kc^(row&7).
// Stage offsets: Ahi 0, Alo 16K, Bhi 32K, Blo 48K.
// ---------------------------------------------------------------------------
#define GSTAGE 65536
#define GEMM_SMEM (2 * GSTAGE)

__device__ __forceinline__ void gemm_tc_body(const __nv_bfloat16* __restrict__ Ah,
                                             const __nv_bfloat16* __restrict__ Al,
                                             const __nv_bfloat16* __restrict__ Bh,
                                             const __nv_bfloat16* __restrict__ Bl,
                                             float* __restrict__ C, int Nn) {
    extern __shared__ __align__(1024) char smem[];
    const uint32_t sb = smem_u32(smem);
    const int tid = threadIdx.x;
    const int wid = tid >> 5, lane = tid & 31;
    const int wm = wid & 3, wn = wid >> 2;
    const int m0 = blockIdx.y << 7, n0 = blockIdx.x << 7;

    float acc[2][8][4];
#pragma unroll
    for (int i = 0; i < 2; i++)
#pragma unroll
        for (int j = 0; j < 8; j++)
#pragma unroll
            for (int k = 0; k < 4; k++) acc[i][j][k] = 0.f;

    // global tile base pointers (bytes); row stride 2048 B, chunk = +128 B
    const char* gp[4] = {
        (const char*)(Ah + (size_t)m0 * NC),
        (const char*)(Al + (size_t)m0 * NC),
        (const char*)(Bh + (size_t)n0 * NC),
        (const char*)(Bl + (size_t)n0 * NC)
    };

    // precomputed per-thread load mapping: 16 cp.async per stage
    uint32_t s_off[16];
    uint32_t g_off[16];
#pragma unroll
    for (int i = 0; i < 16; i++) {
        const int idx = tid + i * 256;
        const int tile = idx >> 10;
        const int cidx = idx & 1023;
        const int row = cidx >> 3, kc8 = cidx & 7;
        s_off[i] = (uint32_t)(tile * 16384 + row * 128 + ((kc8 ^ (row & 7)) << 4));
        g_off[i] = (uint32_t)(row * 2048 + kc8 * 16);
    }

#define LOAD_STAGE(chunk, stage) do {                                        \
    const uint32_t sbase = sb + (stage) * GSTAGE;                            \
    const uint32_t koff = (uint32_t)(chunk) * 128u;                          \
    _Pragma("unroll")                                                        \
    for (int i = 0; i < 16; i++) {                                           \
        const int tile = (tid + i * 256) >> 10;                              \
        cp_async16(sbase + s_off[i], gp[tile] + g_off[i] + koff);            \
    }                                                                        \
    asm volatile("cp.async.commit_group;" ::: "memory");                     \
} while (0)

    // ldmatrix lane-derived address components
    const int a_row = (lane & 7) | (((lane >> 3) & 1) << 3);   // 0..15
    const int a_kc = lane >> 4;                                 // 0..1
    const int b_row = (lane & 7) + ((lane >> 4) << 3);          // 0..15
    const int b_kc = (lane >> 3) & 1;                           // 0..1

    LOAD_STAGE(0, 0);

    for (int ch = 0; ch < 16; ch++) {
        if (ch < 15) {
            LOAD_STAGE(ch + 1, (ch + 1) & 1);
            asm volatile("cp.async.wait_group 1;" ::: "memory");
        } else {
            asm volatile("cp.async.wait_group 0;" ::: "memory");
        }
        __syncthreads();

        const uint32_t st = sb + (ch & 1) * GSTAGE;
        const uint32_t sAh = st, sAl = st + 16384;
        const uint32_t sBh = st + 32768, sBl = st + 49152;

#pragma unroll
        for (int ks = 0; ks < 4; ks++) {
            uint32_t ah[2][4], al[2][4], bh[4][4], bl[4][4];
#pragma unroll
            for (int mi = 0; mi < 2; mi++) {
                const int r = wm * 32 + mi * 16 + a_row;
                const int kc = ks * 2 + a_kc;
                const uint32_t off = (uint32_t)(r * 128 + ((kc ^ (r & 7)) << 4));
                ldsm4(ah[mi], sAh + off);
                ldsm4(al[mi], sAl + off);
            }
#pragma unroll
            for (int gi = 0; gi < 4; gi++) {
                const int r = wn * 64 + gi * 16 + b_row;
                const int kc = ks * 2 + b_kc;
                const uint32_t off = (uint32_t)(r * 128 + ((kc ^ (r & 7)) << 4));
                ldsm4(bh[gi], sBh + off);
                ldsm4(bl[gi], sBl + off);
            }
#pragma unroll
            for (int mi = 0; mi < 2; mi++)
#pragma unroll
                for (int gi = 0; gi < 4; gi++)
#pragma unroll
                    for (int hf = 0; hf < 2; hf++) {
                        float* c = acc[mi][gi * 2 + hf];
                        mma_bf16(c, ah[mi], bh[gi][2 * hf], bh[gi][2 * hf + 1]);
                        mma_bf16(c, ah[mi], bl[gi][2 * hf], bl[gi][2 * hf + 1]);
                        mma_bf16(c, al[mi], bh[gi][2 * hf], bh[gi][2 * hf + 1]);
                    }
        }
        __syncthreads();
    }
#undef LOAD_STAGE

    // Epilogue: c0,c1 -> row g, cols 2t,2t+1; c2,c3 -> row g+8
    const int g4 = lane >> 2, t4 = lane & 3;
#pragma unroll
    for (int mi = 0; mi < 2; mi++) {
#pragma unroll
        for (int a = 0; a < 8; a++) {
            const int row = m0 + wm * 32 + mi * 16 + g4;
            const int col = n0 + wn * 64 + a * 8 + 2 * t4;
            *(float2*)(C + (size_t)row * Nn + col) =
                make_float2(acc[mi][a][0], acc[mi][a][1]);
            *(float2*)(C + (size_t)(row + 8) * Nn + col) =
                make_float2(acc[mi][a][2], acc[mi][a][3]);
        }
    }
}

__global__ __launch_bounds__(256) void qkv_gemm_tc() {
    gemm_tc_body(g_x_hi, g_x_lo, g_wq_hi, g_wq_lo, g_qkv, NF);
}
__global__ __launch_bounds__(256) void proj_gemm_tc(float* __restrict__ out) {
    gemm_tc_body(g_at_hi, g_at_lo, g_wp_hi, g_wp_lo, out, NC);
}

// ---------------------------------------------------------------------------
// Flash attention, fp32, causal (unchanged — passes at 1.2e-6).
// ---------------------------------------------------------------------------
#define KSTR 68
#define ATTN_SMEM ((4096 + 64 * KSTR + 4096) * 4)   // 50176 B

__global__ __launch_bounds__(256) void attn_kernel()
{
    extern __shared__ float fsmem[];
    float* Qs = fsmem;                  // [64][64] transposed [d][q]
    float* Ks = fsmem + 4096;           // [64][68] transposed [d][k]; reused as P
    float* Vs = Ks + 64 * KSTR;         // [64][64] natural [k][d]

    const int tid = threadIdx.x;
    const int tq = tid >> 4;
    const int tk = tid & 15;
    const int bh = blockIdx.y;
    const int b = bh >> 4;
    const int h = bh & 15;
    const int q0 = blockIdx.x << 6;

    const float* base = g_qkv + (long long)b * NT * NF + h * ND;

    {
        const int r = tid >> 4;
        const int d4 = (tid & 15) << 2;
#pragma unroll
        for (int it = 0; it < 4; it++) {
            const int rr = r + it * 16;
            const float4 v = *(const float4*)(base + (long long)(q0 + rr) * NF + d4);
            Qs[(d4 + 0) * 64 + rr] = v.x * 0.125f;
            Qs[(d4 + 1) * 64 + rr] = v.y * 0.125f;
            Qs[(d4 + 2) * 64 + rr] = v.z * 0.125f;
            Qs[(d4 + 3) * 64 + rr] = v.w * 0.125f;
        }
    }

    float o[4][4];
    float mr[4], lr[4];
#pragma unroll
    for (int i = 0; i < 4; i++) {
        mr[i] = -1e30f; lr[i] = 0.f;
#pragma unroll
        for (int j = 0; j < 4; j++) o[i][j] = 0.f;
    }

    const int kbmax = blockIdx.x;
    for (int kb = 0; kb <= kbmax; kb++) {
        {
            const int r = tid >> 4;
            const int d4 = (tid & 15) << 2;
            const float* kp = base + NC + (long long)(kb * 64) * NF;
            const float* vp = base + 2 * NC + (long long)(kb * 64) * NF;
#pragma unroll
            for (int it = 0; it < 4; it++) {
                const int rr = r + it * 16;
                const float4 kv = *(const float4*)(kp + (long long)rr * NF + d4);
                Ks[(d4 + 0) * KSTR + rr] = kv.x;
                Ks[(d4 + 1) * KSTR + rr] = kv.y;
                Ks[(d4 + 2) * KSTR + rr] = kv.z;
                Ks[(d4 + 3) * KSTR + rr] = kv.w;
                const float4 vv = *(const float4*)(vp + (long long)rr * NF + d4);
                *(float4*)(Vs + rr * 64 + d4) = vv;
            }
        }
        __syncthreads();

        float s[4][4];
#pragma unroll
        for (int i = 0; i < 4; i++)
#pragma unroll
            for (int j = 0; j < 4; j++) s[i][j] = 0.f;

#pragma unroll 8
        for (int d = 0; d < 64; d++) {
            const float4 qf = *(const float4*)(Qs + d * 64 + (tq << 2));
            const float4 kf = *(const float4*)(Ks + d * KSTR + (tk << 2));
            const float qa[4] = {qf.x, qf.y, qf.z, qf.w};
            const float ka[4] = {kf.x, kf.y, kf.z, kf.w};
#pragma unroll
            for (int i = 0; i < 4; i++)
#pragma unroll
                for (int j = 0; j < 4; j++)
                    s[i][j] += qa[i] * ka[j];
        }

        if (kb == kbmax) {
#pragma unroll
            for (int i = 0; i < 4; i++)
#pragma unroll
                for (int j = 0; j < 4; j++)
                    if ((tk * 4 + j) > (tq * 4 + i)) s[i][j] = -1e30f;
        }

#pragma unroll
        for (int i = 0; i < 4; i++) {
            float mx = fmaxf(fmaxf(s[i][0], s[i][1]), fmaxf(s[i][2], s[i][3]));
#pragma unroll
            for (int off = 1; off < 16; off <<= 1)
                mx = fmaxf(mx, __shfl_xor_sync(0xffffffffu, mx, off));
            const float mnew = fmaxf(mr[i], mx);
            const float alpha = __expf(mr[i] - mnew);
            float ls = 0.f;
#pragma unroll
            for (int j = 0; j < 4; j++) {
                s[i][j] = __expf(s[i][j] - mnew);
                ls += s[i][j];
            }
#pragma unroll
            for (int off = 1; off < 16; off <<= 1)
                ls += __shfl_xor_sync(0xffffffffu, ls, off);
            lr[i] = lr[i] * alpha + ls;
            mr[i] = mnew;
#pragma unroll
            for (int j = 0; j < 4; j++) o[i][j] *= alpha;
        }

        __syncthreads();
#pragma unroll
        for (int i = 0; i < 4; i++)
            *(float4*)(Ks + (tq * 4 + i) * KSTR + tk * 4) =
                make_float4(s[i][0], s[i][1], s[i][2], s[i][3]);
        __syncthreads();

#pragma unroll 4
        for (int k0 = 0; k0 < 64; k0 += 4) {
            float pf[4][4], vf[4][4];
#pragma unroll
            for (int i = 0; i < 4; i++)
                *(float4*)&pf[i][0] = *(const float4*)(Ks + (tq * 4 + i) * KSTR + k0);
#pragma unroll
            for (int kk = 0; kk < 4; kk++)
                *(float4*)&vf[kk][0] = *(const float4*)(Vs + (k0 + kk) * 64 + (tk << 2));
#pragma unroll
            for (int i = 0; i < 4; i++)
#pragma unroll
                for (int kk = 0; kk < 4; kk++)
#pragma unroll
                    for (int j = 0; j < 4; j++)
                        o[i][j] += pf[i][kk] * vf[kk][j];
        }
        __syncthreads();
    }

#pragma unroll
    for (int i = 0; i < 4; i++) {
        const float inv = 1.0f / lr[i];
        const int t = q0 + tq * 4 + i;
        const float4 r = make_float4(o[i][0] * inv, o[i][1] * inv,
                                     o[i][2] * inv, o[i][3] * inv);
        *(float4*)(g_attn + (long long)(b * NT + t) * NC + h * ND + tk * 4) = r;
    }
}

// ---------------------------------------------------------------------------
// Launch pipeline (default stream, graph-capturable)
// ---------------------------------------------------------------------------
extern "C" void kernel_launch(void* const* d_in, const int* in_sizes, int n_in,
                              void* d_out, int out_size)
{
    const float* x      = (const float*)d_in[0];
    const float* w_qkv  = (const float*)d_in[1];
    const float* w_proj = (const float*)d_in[2];
    float* out = (float*)d_out;

    cudaFuncSetAttribute(qkv_gemm_tc,
                         cudaFuncAttributeMaxDynamicSharedMemorySize, GEMM_SMEM);
    cudaFuncSetAttribute(proj_gemm_tc,
                         cudaFuncAttributeMaxDynamicSharedMemorySize, GEMM_SMEM);
    cudaFuncSetAttribute(attn_kernel,
                         cudaFuncAttributeMaxDynamicSharedMemorySize, ATTN_SMEM);

    split_x<<<NM, 256>>>(x);
    split_wq<<<NF, 256>>>(w_qkv);
    split_wp<<<NC, 256>>>(w_proj);

    qkv_gemm_tc<<<dim3(NF / 128, NM / 128), 256, GEMM_SMEM>>>();

    attn_kernel<<<dim3(NT / 64, NB * NH), 256, ATTN_SMEM>>>();

    split_at<<<NM, 256>>>();
    proj_gemm_tc<<<dim3(NC / 128, NM / 128), 256, GEMM_SMEM>>>(out);
}

// round 6
// speedup vs baseline: 2.9974x; 1.8862x over previous
#include <cuda_runtime.h>
#include <cuda_bf16.h>
#include <cstdint>

// Problem constants
#define NB 4
#define NT 2048
#define NC 1024
#define NH 16
#define ND 64
#define NM (NB * NT)     // 8192 rows
#define NF (3 * NC)      // 3072 qkv features

// ---------------------------------------------------------------------------
// Scratch (__device__ globals)
// ---------------------------------------------------------------------------
// qkv output, split bf16 hi/lo, row-major [8192][3072]. Q cols pre-scaled 0.125.
__device__ __nv_bfloat16 g_qkvh[NM * NF], g_qkvl[NM * NF];
// attention output, split bf16 hi/lo, row-major [8192][1024]
__device__ __nv_bfloat16 g_at_hi[NM * NC], g_at_lo[NM * NC];
// GEMM input splits
__device__ __nv_bfloat16 g_x_hi[NM * NC],  g_x_lo[NM * NC];
__device__ __nv_bfloat16 g_wq_hi[NF * NC], g_wq_lo[NF * NC];
__device__ __nv_bfloat16 g_wp_hi[NC * NC], g_wp_lo[NC * NC];

// ---------------------------------------------------------------------------
// PTX helpers (arch-agnostic: mma.sync / ldmatrix / cp.async only)
// ---------------------------------------------------------------------------
__device__ __forceinline__ uint32_t smem_u32(const void* p) {
    uint32_t a;
    asm("{ .reg .u64 t; cvta.to.shared.u64 t, %1; cvt.u32.u64 %0, t; }"
        : "=r"(a) : "l"(p));
    return a;
}

__device__ __forceinline__ void cp_async16(uint32_t dst, const void* src) {
    asm volatile("cp.async.cg.shared.global [%0], [%1], 16;" :: "r"(dst), "l"(src));
}

__device__ __forceinline__ void ldsm4(uint32_t* r, uint32_t addr) {
    asm volatile("ldmatrix.sync.aligned.m8n8.x4.shared.b16 {%0,%1,%2,%3}, [%4];"
                 : "=r"(r[0]), "=r"(r[1]), "=r"(r[2]), "=r"(r[3]) : "r"(addr));
}

__device__ __forceinline__ void ldsm4t(uint32_t* r, uint32_t addr) {
    asm volatile("ldmatrix.sync.aligned.m8n8.x4.trans.shared.b16 {%0,%1,%2,%3}, [%4];"
                 : "=r"(r[0]), "=r"(r[1]), "=r"(r[2]), "=r"(r[3]) : "r"(addr));
}

__device__ __forceinline__ void mma_bf16(float* c, const uint32_t* a,
                                         uint32_t b0, uint32_t b1) {
    asm volatile(
        "mma.sync.aligned.m16n8k16.row.col.f32.bf16.bf16.f32 "
        "{%0,%1,%2,%3}, {%4,%5,%6,%7}, {%8,%9}, {%0,%1,%2,%3};"
        : "+f"(c[0]), "+f"(c[1]), "+f"(c[2]), "+f"(c[3])
        : "r"(a[0]), "r"(a[1]), "r"(a[2]), "r"(a[3]), "r"(b0), "r"(b1));
}

// pack two floats as bf16 pair {lo half = v0, hi half = v1}
__device__ __forceinline__ uint32_t pack_bf16(float v0, float v1) {
    const __nv_bfloat16 a = __float2bfloat16(v0), b = __float2bfloat16(v1);
    return (uint32_t)__bfloat16_as_ushort(a) | ((uint32_t)__bfloat16_as_ushort(b) << 16);
}

// hi/lo split of a pair of floats -> packed hi word + packed lo word
__device__ __forceinline__ void split2(float v0, float v1,
                                       uint32_t& uh, uint32_t& ul) {
    const __nv_bfloat16 h0 = __float2bfloat16(v0);
    const __nv_bfloat16 h1 = __float2bfloat16(v1);
    const float r0 = v0 - __bfloat162float(h0);
    const float r1 = v1 - __bfloat162float(h1);
    const __nv_bfloat16 l0 = __float2bfloat16(r0);
    const __nv_bfloat16 l1 = __float2bfloat16(r1);
    uh = (uint32_t)__bfloat16_as_ushort(h0) | ((uint32_t)__bfloat16_as_ushort(h1) << 16);
    ul = (uint32_t)__bfloat16_as_ushort(l0) | ((uint32_t)__bfloat16_as_ushort(l1) << 16);
}

// ---------------------------------------------------------------------------
// Split prep for GEMM inputs: fp32 [R][1024] -> hi/lo bf16 row-major.
// ---------------------------------------------------------------------------
__device__ __forceinline__ void split_body(const float* __restrict__ src,
                                           __nv_bfloat16* __restrict__ hi,
                                           __nv_bfloat16* __restrict__ lo) {
    const int r = blockIdx.x;
    const int c4 = threadIdx.x << 2;
    const float4 v = *(const float4*)(src + (size_t)r * NC + c4);
    uint2 uh, ul;
    split2(v.x, v.y, uh.x, ul.x);
    split2(v.z, v.w, uh.y, ul.y);
    *(uint2*)(hi + (size_t)r * NC + c4) = uh;
    *(uint2*)(lo + (size_t)r * NC + c4) = ul;
}

__global__ __launch_bounds__(256) void split_x(const float* __restrict__ s)  { split_body(s, g_x_hi,  g_x_lo);  }
__global__ __launch_bounds__(256) void split_wq(const float* __restrict__ s) { split_body(s, g_wq_hi, g_wq_lo); }
__global__ __launch_bounds__(256) void split_wp(const float* __restrict__ s) { split_body(s, g_wp_hi, g_wp_lo); }

// ---------------------------------------------------------------------------
// mma.sync GEMM: C[m][n] = sum_k A[m][k]*B[n][k] (fp32 via bf16 2-term split)
// CTA 128x128, 256 thr, warp tile 32x64, BK=64, double-buffered cp.async.
// SPLIT_OUT=0: fp32 C.  SPLIT_OUT=1: bf16 hi/lo C, cols<1024 scaled by 0.125.
// ---------------------------------------------------------------------------
#define GSTAGE 65536
#define GEMM_SMEM (2 * GSTAGE)

template <int SPLIT_OUT>
__device__ __forceinline__ void gemm_tc_body(const __nv_bfloat16* __restrict__ Ah,
                                             const __nv_bfloat16* __restrict__ Al,
                                             const __nv_bfloat16* __restrict__ Bh,
                                             const __nv_bfloat16* __restrict__ Bl,
                                             float* __restrict__ C,
                                             __nv_bfloat16* __restrict__ Ch,
                                             __nv_bfloat16* __restrict__ Cl,
                                             int Nn) {
    extern __shared__ __align__(1024) char smem[];
    const uint32_t sb = smem_u32(smem);
    const int tid = threadIdx.x;
    const int wid = tid >> 5, lane = tid & 31;
    const int wm = wid & 3, wn = wid >> 2;
    const int m0 = blockIdx.y << 7, n0 = blockIdx.x << 7;

    float acc[2][8][4];
#pragma unroll
    for (int i = 0; i < 2; i++)
#pragma unroll
        for (int j = 0; j < 8; j++)
#pragma unroll
            for (int k = 0; k < 4; k++) acc[i][j][k] = 0.f;

    const char* gp[4] = {
        (const char*)(Ah + (size_t)m0 * NC),
        (const char*)(Al + (size_t)m0 * NC),
        (const char*)(Bh + (size_t)n0 * NC),
        (const char*)(Bl + (size_t)n0 * NC)
    };

    uint32_t s_off[16];
    uint32_t g_off[16];
#pragma unroll
    for (int i = 0; i < 16; i++) {
        const int idx = tid + i * 256;
        const int tile = idx >> 10;
        const int cidx = idx & 1023;
        const int row = cidx >> 3, kc8 = cidx & 7;
        s_off[i] = (uint32_t)(tile * 16384 + row * 128 + ((kc8 ^ (row & 7)) << 4));
        g_off[i] = (uint32_t)(row * 2048 + kc8 * 16);
    }

#define LOAD_STAGE(chunk, stage) do {                                        \
    const uint32_t sbase = sb + (stage) * GSTAGE;                            \
    const uint32_t koff = (uint32_t)(chunk) * 128u;                          \
    _Pragma("unroll")                                                        \
    for (int i = 0; i < 16; i++) {                                           \
        const int tile = (tid + i * 256) >> 10;                              \
        cp_async16(sbase + s_off[i], gp[tile] + g_off[i] + koff);            \
    }                                                                        \
    asm volatile("cp.async.commit_group;" ::: "memory");                     \
} while (0)

    const int a_row = (lane & 7) | (((lane >> 3) & 1) << 3);
    const int a_kc = lane >> 4;
    const int b_row = (lane & 7) + ((lane >> 4) << 3);
    const int b_kc = (lane >> 3) & 1;

    LOAD_STAGE(0, 0);

    for (int ch = 0; ch < 16; ch++) {
        if (ch < 15) {
            LOAD_STAGE(ch + 1, (ch + 1) & 1);
            asm volatile("cp.async.wait_group 1;" ::: "memory");
        } else {
            asm volatile("cp.async.wait_group 0;" ::: "memory");
        }
        __syncthreads();

        const uint32_t st = sb + (ch & 1) * GSTAGE;
        const uint32_t sAh = st, sAl = st + 16384;
        const uint32_t sBh = st + 32768, sBl = st + 49152;

#pragma unroll
        for (int ks = 0; ks < 4; ks++) {
            uint32_t ah[2][4], al[2][4], bh[4][4], bl[4][4];
#pragma unroll
            for (int mi = 0; mi < 2; mi++) {
                const int r = wm * 32 + mi * 16 + a_row;
                const int kc = ks * 2 + a_kc;
                const uint32_t off = (uint32_t)(r * 128 + ((kc ^ (r & 7)) << 4));
                ldsm4(ah[mi], sAh + off);
                ldsm4(al[mi], sAl + off);
            }
#pragma unroll
            for (int gi = 0; gi < 4; gi++) {
                const int r = wn * 64 + gi * 16 + b_row;
                const int kc = ks * 2 + b_kc;
                const uint32_t off = (uint32_t)(r * 128 + ((kc ^ (r & 7)) << 4));
                ldsm4(bh[gi], sBh + off);
                ldsm4(bl[gi], sBl + off);
            }
#pragma unroll
            for (int mi = 0; mi < 2; mi++)
#pragma unroll
                for (int gi = 0; gi < 4; gi++)
#pragma unroll
                    for (int hf = 0; hf < 2; hf++) {
                        float* c = acc[mi][gi * 2 + hf];
                        mma_bf16(c, ah[mi], bh[gi][2 * hf], bh[gi][2 * hf + 1]);
                        mma_bf16(c, ah[mi], bl[gi][2 * hf], bl[gi][2 * hf + 1]);
                        mma_bf16(c, al[mi], bh[gi][2 * hf], bh[gi][2 * hf + 1]);
                    }
        }
        __syncthreads();
    }
#undef LOAD_STAGE

    const int g4 = lane >> 2, t4 = lane & 3;
#pragma unroll
    for (int mi = 0; mi < 2; mi++) {
#pragma unroll
        for (int a = 0; a < 8; a++) {
            const int row = m0 + wm * 32 + mi * 16 + g4;
            const int col = n0 + wn * 64 + a * 8 + 2 * t4;
            if (SPLIT_OUT) {
                const float sc = (col < NC) ? 0.125f : 1.0f;   // scale Q third
                uint32_t uh, ul;
                split2(acc[mi][a][0] * sc, acc[mi][a][1] * sc, uh, ul);
                *(uint32_t*)(Ch + (size_t)row * Nn + col) = uh;
                *(uint32_t*)(Cl + (size_t)row * Nn + col) = ul;
                split2(acc[mi][a][2] * sc, acc[mi][a][3] * sc, uh, ul);
                *(uint32_t*)(Ch + (size_t)(row + 8) * Nn + col) = uh;
                *(uint32_t*)(Cl + (size_t)(row + 8) * Nn + col) = ul;
            } else {
                *(float2*)(C + (size_t)row * Nn + col) =
                    make_float2(acc[mi][a][0], acc[mi][a][1]);
                *(float2*)(C + (size_t)(row + 8) * Nn + col) =
                    make_float2(acc[mi][a][2], acc[mi][a][3]);
            }
        }
    }
}

__global__ __launch_bounds__(256) void qkv_gemm_tc() {
    gemm_tc_body<1>(g_x_hi, g_x_lo, g_wq_hi, g_wq_lo,
                    nullptr, g_qkvh, g_qkvl, NF);
}
__global__ __launch_bounds__(256) void proj_gemm_tc(float* __restrict__ out) {
    gemm_tc_body<0>(g_at_hi, g_at_lo, g_wp_hi, g_wp_lo,
                    out, nullptr, nullptr, NC);
}

// ---------------------------------------------------------------------------
// Tensor-core flash attention (bf16 hi/lo split, fp32 softmax).
// CTA: 128 thr (4 warps), 64 q-rows; warp w owns rows w*16..w*16+15.
// K-chunks of 64 keys, double-buffered cp.async (2 x 32KB).
// Smem stage: Kh[64][64] Kl Vh Vl bf16, 128B rows, chunk swizzle c^(row&7).
// Q fragments loaded once from gmem. P re-split in registers for PV MMA.
// Epilogue writes split bf16 directly (proj GEMM input).
// ---------------------------------------------------------------------------
#define ASTAGE 32768
#define ATTN_SMEM (2 * ASTAGE)

__global__ __launch_bounds__(128) void attn_tc_kernel()
{
    extern __shared__ __align__(1024) char asmem[];
    const uint32_t sb = smem_u32(asmem);
    const int tid = threadIdx.x;
    const int w = tid >> 5, lane = tid & 31;
    const int g = lane >> 2, t = lane & 3;
    const int bh = blockIdx.y;
    const int b = bh >> 4, h = bh & 15;
    const int q0 = blockIdx.x << 6;
    const int t0base = b * NT;            // row offset of this batch in g_qkv*

    // --- Q fragments (registers, loaded once). Rows qr0 = q0+w*16+g, qr1=+8.
    const int qr0 = t0base + q0 + w * 16 + g;
    const __nv_bfloat16* qh0 = g_qkvh + (size_t)qr0 * NF + h * ND;
    const __nv_bfloat16* qh1 = qh0 + 8 * NF;
    const __nv_bfloat16* ql0 = g_qkvl + (size_t)qr0 * NF + h * ND;
    const __nv_bfloat16* ql1 = ql0 + 8 * NF;

    uint32_t qa_h[4][4], qa_l[4][4];
#pragma unroll
    for (int s = 0; s < 4; s++) {
        qa_h[s][0] = *(const uint32_t*)(qh0 + s * 16 + 2 * t);
        qa_h[s][1] = *(const uint32_t*)(qh1 + s * 16 + 2 * t);
        qa_h[s][2] = *(const uint32_t*)(qh0 + s * 16 + 8 + 2 * t);
        qa_h[s][3] = *(const uint32_t*)(qh1 + s * 16 + 8 + 2 * t);
        qa_l[s][0] = *(const uint32_t*)(ql0 + s * 16 + 2 * t);
        qa_l[s][1] = *(const uint32_t*)(ql1 + s * 16 + 2 * t);
        qa_l[s][2] = *(const uint32_t*)(ql0 + s * 16 + 8 + 2 * t);
        qa_l[s][3] = *(const uint32_t*)(ql1 + s * 16 + 8 + 2 * t);
    }

    // --- O accumulators + softmax stats
    float oc[8][4];
#pragma unroll
    for (int nf = 0; nf < 8; nf++)
#pragma unroll
        for (int k = 0; k < 4; k++) oc[nf][k] = 0.f;
    float m0 = -1e30f, m1 = -1e30f, l0 = 0.f, l1 = 0.f;

    // K/V chunk loader: 2048 x 16B per chunk over 128 threads.
#define ALOAD(kb_, st_) do {                                                  \
    const uint32_t sbase = sb + (uint32_t)(st_) * ASTAGE;                     \
    const size_t trow = (size_t)t0base + (size_t)(kb_) * 64;                  \
    _Pragma("unroll")                                                         \
    for (int i = 0; i < 16; i++) {                                            \
        const int idx = tid + i * 128;                                        \
        const int arr = idx >> 9;                                             \
        const int rem = idx & 511;                                            \
        const int row = rem >> 3, c8 = rem & 7;                               \
        const __nv_bfloat16* src = ((arr & 1) ? g_qkvl : g_qkvh)              \
            + (trow + row) * NF + ((arr < 2) ? NC : 2 * NC) + h * ND + c8 * 8;\
        cp_async16(sbase + arr * 8192 + row * 128 + ((c8 ^ (row & 7)) << 4),  \
                   src);                                                      \
    }                                                                         \
    asm volatile("cp.async.commit_group;" ::: "memory");                      \
} while (0)

    const int nchunks = blockIdx.x + 1;
    ALOAD(0, 0);

    // ldmatrix lane address components
    const int b_row = (lane & 7) + ((lane >> 4) << 3);   // S B-frags (non-trans)
    const int b_kc = (lane >> 3) & 1;
    const int v_row = (lane & 7) + (((lane >> 3) & 1) << 3);  // V B-frags (trans)
    const int v_cg = lane >> 4;

    for (int kb = 0; kb < nchunks; kb++) {
        if (kb + 1 < nchunks) {
            ALOAD(kb + 1, (kb + 1) & 1);
            asm volatile("cp.async.wait_group 1;" ::: "memory");
        } else {
            asm volatile("cp.async.wait_group 0;" ::: "memory");
        }
        __syncthreads();

        const uint32_t st = sb + (uint32_t)(kb & 1) * ASTAGE;
        const uint32_t sKh = st, sKl = st + 8192;
        const uint32_t sVh = st + 16384, sVl = st + 24576;

        // ---- S = Q K^T (3-term split), fragments sc[8][4]
        float sc[8][4];
#pragma unroll
        for (int nf = 0; nf < 8; nf++)
#pragma unroll
            for (int k = 0; k < 4; k++) sc[nf][k] = 0.f;

#pragma unroll
        for (int s = 0; s < 4; s++) {
            uint32_t kbh[4][4], kbl[4][4];
#pragma unroll
            for (int gi = 0; gi < 4; gi++) {
                const int r = gi * 16 + b_row;
                const int kc = s * 2 + b_kc;
                const uint32_t off = (uint32_t)(r * 128 + ((kc ^ (r & 7)) << 4));
                ldsm4(kbh[gi], sKh + off);
                ldsm4(kbl[gi], sKl + off);
            }
#pragma unroll
            for (int gi = 0; gi < 4; gi++)
#pragma unroll
                for (int hf = 0; hf < 2; hf++) {
                    float* c = sc[gi * 2 + hf];
                    mma_bf16(c, qa_h[s], kbh[gi][2 * hf], kbh[gi][2 * hf + 1]);
                    mma_bf16(c, qa_h[s], kbl[gi][2 * hf], kbl[gi][2 * hf + 1]);
                    mma_bf16(c, qa_l[s], kbh[gi][2 * hf], kbh[gi][2 * hf + 1]);
                }
        }

        // ---- causal mask (diagonal chunk only)
        if (kb == nchunks - 1) {
            const int r0 = q0 + w * 16 + g;       // local query rows
            const int r1 = r0 + 8;
#pragma unroll
            for (int nf = 0; nf < 8; nf++) {
                const int c0 = kb * 64 + nf * 8 + 2 * t;
                if (c0 > r0)     sc[nf][0] = -1e30f;
                if (c0 + 1 > r0) sc[nf][1] = -1e30f;
                if (c0 > r1)     sc[nf][2] = -1e30f;
                if (c0 + 1 > r1) sc[nf][3] = -1e30f;
            }
        }

        // ---- online softmax (rows g and g+8)
        float mx0 = -1e30f, mx1 = -1e30f;
#pragma unroll
        for (int nf = 0; nf < 8; nf++) {
            mx0 = fmaxf(mx0, fmaxf(sc[nf][0], sc[nf][1]));
            mx1 = fmaxf(mx1, fmaxf(sc[nf][2], sc[nf][3]));
        }
        mx0 = fmaxf(mx0, __shfl_xor_sync(0xffffffffu, mx0, 1));
        mx0 = fmaxf(mx0, __shfl_xor_sync(0xffffffffu, mx0, 2));
        mx1 = fmaxf(mx1, __shfl_xor_sync(0xffffffffu, mx1, 1));
        mx1 = fmaxf(mx1, __shfl_xor_sync(0xffffffffu, mx1, 2));

        const float mn0 = fmaxf(m0, mx0), mn1 = fmaxf(m1, mx1);
        const float al0 = __expf(m0 - mn0), al1 = __expf(m1 - mn1);
        float sum0 = 0.f, sum1 = 0.f;
#pragma unroll
        for (int nf = 0; nf < 8; nf++) {
            sc[nf][0] = __expf(sc[nf][0] - mn0);
            sc[nf][1] = __expf(sc[nf][1] - mn0);
            sc[nf][2] = __expf(sc[nf][2] - mn1);
            sc[nf][3] = __expf(sc[nf][3] - mn1);
            sum0 += sc[nf][0] + sc[nf][1];
            sum1 += sc[nf][2] + sc[nf][3];
        }
        sum0 += __shfl_xor_sync(0xffffffffu, sum0, 1);
        sum0 += __shfl_xor_sync(0xffffffffu, sum0, 2);
        sum1 += __shfl_xor_sync(0xffffffffu, sum1, 1);
        sum1 += __shfl_xor_sync(0xffffffffu, sum1, 2);
        l0 = l0 * al0 + sum0;  m0 = mn0;
        l1 = l1 * al1 + sum1;  m1 = mn1;
#pragma unroll
        for (int nf = 0; nf < 8; nf++) {
            oc[nf][0] *= al0; oc[nf][1] *= al0;
            oc[nf][2] *= al1; oc[nf][3] *= al1;
        }

        // ---- O += P V (P split hi/lo in registers; V via ldmatrix.trans)
#pragma unroll
        for (int s = 0; s < 4; s++) {
            uint32_t pa_h[4], pa_l[4];
            split2(sc[2 * s][0],     sc[2 * s][1],     pa_h[0], pa_l[0]);
            split2(sc[2 * s][2],     sc[2 * s][3],     pa_h[1], pa_l[1]);
            split2(sc[2 * s + 1][0], sc[2 * s + 1][1], pa_h[2], pa_l[2]);
            split2(sc[2 * s + 1][2], sc[2 * s + 1][3], pa_h[3], pa_l[3]);

#pragma unroll
            for (int ng = 0; ng < 4; ng++) {
                const int r = s * 16 + v_row;
                const int kc = ng * 2 + v_cg;
                const uint32_t off = (uint32_t)(r * 128 + ((kc ^ (r & 7)) << 4));
                uint32_t vbh[4], vbl[4];
                ldsm4t(vbh, sVh + off);
                ldsm4t(vbl, sVl + off);
#pragma unroll
                for (int hf = 0; hf < 2; hf++) {
                    float* c = oc[ng * 2 + hf];
                    mma_bf16(c, pa_h, vbh[2 * hf], vbh[2 * hf + 1]);
                    mma_bf16(c, pa_h, vbl[2 * hf], vbl[2 * hf + 1]);
                    mma_bf16(c, pa_l, vbh[2 * hf], vbh[2 * hf + 1]);
                }
            }
        }
        __syncthreads();
    }
#undef ALOAD

    // ---- epilogue: normalize, split bf16, write proj input
    const float inv0 = 1.0f / l0, inv1 = 1.0f / l1;
    __nv_bfloat16* oh0 = g_at_hi + (size_t)qr0 * NC + h * ND;
    __nv_bfloat16* ol0 = g_at_lo + (size_t)qr0 * NC + h * ND;
#pragma unroll
    for (int nf = 0; nf < 8; nf++) {
        const int col = nf * 8 + 2 * t;
        uint32_t uh, ul;
        split2(oc[nf][0] * inv0, oc[nf][1] * inv0, uh, ul);
        *(uint32_t*)(oh0 + col) = uh;
        *(uint32_t*)(ol0 + col) = ul;
        split2(oc[nf][2] * inv1, oc[nf][3] * inv1, uh, ul);
        *(uint32_t*)(oh0 + 8 * NC + col) = uh;
        *(uint32_t*)(ol0 + 8 * NC + col) = ul;
    }
}

// ---------------------------------------------------------------------------
// Launch pipeline (default stream, graph-capturable)
// ---------------------------------------------------------------------------
extern "C" void kernel_launch(void* const* d_in, const int* in_sizes, int n_in,
                              void* d_out, int out_size)
{
    const float* x      = (const float*)d_in[0];
    const float* w_qkv  = (const float*)d_in[1];
    const float* w_proj = (const float*)d_in[2];
    float* out = (float*)d_out;

    cudaFuncSetAttribute(qkv_gemm_tc,
                         cudaFuncAttributeMaxDynamicSharedMemorySize, GEMM_SMEM);
    cudaFuncSetAttribute(proj_gemm_tc,
                         cudaFuncAttributeMaxDynamicSharedMemorySize, GEMM_SMEM);
    cudaFuncSetAttribute(attn_tc_kernel,
                         cudaFuncAttributeMaxDynamicSharedMemorySize, ATTN_SMEM);

    split_x<<<NM, 256>>>(x);
    split_wq<<<NF, 256>>>(w_qkv);
    split_wp<<<NC, 256>>>(w_proj);

    qkv_gemm_tc<<<dim3(NF / 128, NM / 128), 256, GEMM_SMEM>>>();

    attn_tc_kernel<<<dim3(NT / 64, NB * NH), 128, ATTN_SMEM>>>();

    proj_gemm_tc<<<dim3(NC / 128, NM / 128), 256, GEMM_SMEM>>>(out);
}